// round 9
// baseline (speedup 1.0000x reference)
#include <cuda_runtime.h>
#include <cuda_bf16.h>
#include <cuda_fp16.h>
#include <math.h>

// ---------------------------------------------------------------------------
// QuantumAttention, analytic circuit collapse:
//   z_i = cos(x_i + p_i); proj[0] = z1..z7 ; proj[w>=1] = z0..zw
// Attention: QK^T tf32 mma -> f16x2 ex2 softmax (no max, |s|<=2.83) ->
// P@V f16 m16n8k16 mma (packed ex2 output IS the A-fragment) + ones-mma
// for the denominator (exact f32, no shuffles). Combine: split-tf32 GEMM.
// ---------------------------------------------------------------------------

#define NROWS   65536
#define S_LEN   1024
#define NHEADS  64
#define DK      8
#define E_DIM   128
#define NROWS_E 4096

__device__ float g_qkv[NROWS * DK];       // [b,h,s,d] head-major
__device__ float g_attn[NROWS_E * E_DIM]; // [b,s,e]
__device__ uint4 g_wb[16 * 16 * 32];      // W packed as split B-fragments

__device__ __forceinline__ unsigned tf32_of(float f) {
    unsigned u; asm("cvt.rna.tf32.f32 %0, %1;" : "=r"(u) : "f"(f));
    return u;
}
__device__ __forceinline__ unsigned h2_of(float lo, float hi) {
    __half2 h = __floats2half2_rn(lo, hi);
    return *reinterpret_cast<unsigned*>(&h);
}
__device__ __forceinline__ unsigned ex2_h2(unsigned s) {
    __half2 h = h2exp2(*reinterpret_cast<__half2*>(&s));
    return *reinterpret_cast<unsigned*>(&h);
}
// tf32 m16n8k8, C = A*B
__device__ __forceinline__ void mma8(float& c0, float& c1, float& c2, float& c3,
                                     unsigned a0, unsigned a1, unsigned a2, unsigned a3,
                                     unsigned b0, unsigned b1) {
    asm("mma.sync.aligned.m16n8k8.row.col.f32.tf32.tf32.f32 "
        "{%0,%1,%2,%3},{%4,%5,%6,%7},{%8,%9},{%10,%11,%12,%13};"
        : "=f"(c0), "=f"(c1), "=f"(c2), "=f"(c3)
        : "r"(a0), "r"(a1), "r"(a2), "r"(a3), "r"(b0), "r"(b1),
          "f"(0.f), "f"(0.f), "f"(0.f), "f"(0.f));
}
// tf32 m16n8k8, C += A*B
__device__ __forceinline__ void mma8_acc(float& c0, float& c1, float& c2, float& c3,
                                         unsigned a0, unsigned a1, unsigned a2, unsigned a3,
                                         unsigned b0, unsigned b1) {
    asm("mma.sync.aligned.m16n8k8.row.col.f32.tf32.tf32.f32 "
        "{%0,%1,%2,%3},{%4,%5,%6,%7},{%8,%9},{%0,%1,%2,%3};"
        : "+f"(c0), "+f"(c1), "+f"(c2), "+f"(c3)
        : "r"(a0), "r"(a1), "r"(a2), "r"(a3), "r"(b0), "r"(b1));
}
// f16 m16n8k16, C += A*B  (A,B packed f16x2; C f32)
__device__ __forceinline__ void mma16h_acc(float& c0, float& c1, float& c2, float& c3,
                                           unsigned a0, unsigned a1, unsigned a2, unsigned a3,
                                           unsigned b0, unsigned b1) {
    asm("mma.sync.aligned.m16n8k16.row.col.f32.f16.f16.f32 "
        "{%0,%1,%2,%3},{%4,%5,%6,%7},{%8,%9},{%0,%1,%2,%3};"
        : "+f"(c0), "+f"(c1), "+f"(c2), "+f"(c3)
        : "r"(a0), "r"(a1), "r"(a2), "r"(a3), "r"(b0), "r"(b1));
}

// ---------------------------------------------------------------------------
// Kernel 1: quantum projection
// ---------------------------------------------------------------------------
__global__ void qkv_kernel(const float* __restrict__ x,
                           const float* __restrict__ rx) {
    int r = blockIdx.x * blockDim.x + threadIdx.x;
    if (r >= NROWS) return;

    float pv[8];
#pragma unroll
    for (int i = 0; i < 8; i++) pv[i] = __ldg(rx + i);

    const float4* xr = reinterpret_cast<const float4*>(x + (size_t)r * DK);
    float4 x0 = xr[0];
    float4 x1 = xr[1];

    float z0 = __cosf(x0.x + pv[0]);
    float z1 = __cosf(x0.y + pv[1]);
    float z2 = __cosf(x0.z + pv[2]);
    float z3 = __cosf(x0.w + pv[3]);
    float z4 = __cosf(x1.x + pv[4]);
    float z5 = __cosf(x1.y + pv[5]);
    float z6 = __cosf(x1.z + pv[6]);
    float z7 = __cosf(x1.w + pv[7]);

    float o1 = z0 * z1;
    float o2 = o1 * z2;
    float o3 = o2 * z3;
    float o4 = o3 * z4;
    float o5 = o4 * z5;
    float o6 = o5 * z6;
    float o7 = o6 * z7;
    float o0 = z1 * z2;
    o0 *= z3; o0 *= z4; o0 *= z5; o0 *= z6; o0 *= z7;

    int h  = r & 15;
    int bs = r >> 4;
    int bb = bs >> 10;
    int s  = bs & 1023;
    int dst = ((bb << 4) + h) * S_LEN + s;

    float4* out = reinterpret_cast<float4*>(g_qkv + (size_t)dst * DK);
    out[0] = make_float4(o0, o1, o2, o3);
    out[1] = make_float4(o4, o5, o6, o7);
}

// ---------------------------------------------------------------------------
// Kernel 2: attention. Block = 256 threads (8 warps x 16 q rows) x 1024 keys.
// sKt: tf32, row r: [d0,d4, d1,d5, d2,d6, d3,d7]  (QK B-frags + Q A-frags)
// sVh: f16x2, pair j word d = (V[2j][d], V[2j+1][d])  (PV B-frags)
// Score col n of QK mma = key kb+n; PV A-frag = h2exp2 packed QK output.
// Denominator via f16 mma against all-ones B (exact f32 accum, per-thread).
// ---------------------------------------------------------------------------
__global__ __launch_bounds__(256) void attn_kernel() {
    __shared__ __align__(16) unsigned sKt[S_LEN * DK];        // 32 KB
    __shared__ __align__(16) unsigned sVh[(S_LEN / 2) * DK];  // 16 KB

    int head = blockIdx.x >> 3;
    int qt   = blockIdx.x & 7;
    int tid  = threadIdx.x;
    int w    = tid >> 5;
    int lane = tid & 31;
    int g    = lane >> 2;
    int t4   = lane & 3;

    // ---- build shared K (tf32) and V (f16x2 pairs): 512 pairs, 2/thread ----
    const float4* Kg4 = reinterpret_cast<const float4*>(g_qkv + (size_t)head * S_LEN * DK);
#pragma unroll
    for (int i = 0; i < 2; i++) {
        int j = tid + i * 256;                  // pair index: rows 2j, 2j+1
        float4 a0 = Kg4[4 * j + 0];             // row 2j   dims 0-3
        float4 a1 = Kg4[4 * j + 1];             // row 2j   dims 4-7
        float4 b0 = Kg4[4 * j + 2];             // row 2j+1 dims 0-3
        float4 b1 = Kg4[4 * j + 3];             // row 2j+1 dims 4-7
        uint4* d0 = reinterpret_cast<uint4*>(sKt + (2 * j) * 8);
        d0[0] = make_uint4(tf32_of(a0.x), tf32_of(a1.x), tf32_of(a0.y), tf32_of(a1.y));
        d0[1] = make_uint4(tf32_of(a0.z), tf32_of(a1.z), tf32_of(a0.w), tf32_of(a1.w));
        uint4* d1 = reinterpret_cast<uint4*>(sKt + (2 * j + 1) * 8);
        d1[0] = make_uint4(tf32_of(b0.x), tf32_of(b1.x), tf32_of(b0.y), tf32_of(b1.y));
        d1[1] = make_uint4(tf32_of(b0.z), tf32_of(b1.z), tf32_of(b0.w), tf32_of(b1.w));
        uint4* vd = reinterpret_cast<uint4*>(sVh + j * 8);
        vd[0] = make_uint4(h2_of(a0.x, b0.x), h2_of(a0.y, b0.y),
                           h2_of(a0.z, b0.z), h2_of(a0.w, b0.w));
        vd[1] = make_uint4(h2_of(a1.x, b1.x), h2_of(a1.y, b1.y),
                           h2_of(a1.z, b1.z), h2_of(a1.w, b1.w));
    }
    __syncthreads();

    const float scale = 0.35355339059327373f * 1.4426950408889634f; // log2e/sqrt8

    // ---- Q A-frag (m16n8k8): rows g, g+8 of this warp's 16-row tile ----
    int ar = qt * 128 + w * 16 + g;
    uint2 q0 = *reinterpret_cast<const uint2*>(sKt + ar * 8 + 2 * t4);
    uint2 q1 = *reinterpret_cast<const uint2*>(sKt + (ar + 8) * 8 + 2 * t4);
    unsigned A0 = tf32_of(__uint_as_float(q0.x) * scale);
    unsigned A1 = tf32_of(__uint_as_float(q1.x) * scale);
    unsigned A2 = tf32_of(__uint_as_float(q0.y) * scale);
    unsigned A3 = tf32_of(__uint_as_float(q1.y) * scale);

    float O0 = 0.f, O1 = 0.f, O2 = 0.f, O3 = 0.f;   // P@V   (rows g,g+8 x dims 2t4,2t4+1)
    float L0 = 0.f, L1 = 0.f, L2 = 0.f, L3 = 0.f;   // P@1   (denominators)
    const unsigned BONE = 0x3C003C00u;              // f16x2 {1,1}

#pragma unroll 2
    for (int kb = 0; kb < S_LEN; kb += 16) {
        uint2 kf0 = *reinterpret_cast<const uint2*>(sKt + (kb + g) * 8 + 2 * t4);
        uint2 kf1 = *reinterpret_cast<const uint2*>(sKt + (kb + 8 + g) * 8 + 2 * t4);

        float c0, c1, c2, c3, d0, d1, d2, d3;
        mma8(c0, c1, c2, c3, A0, A1, A2, A3, kf0.x, kf0.y);   // keys kb..kb+7
        mma8(d0, d1, d2, d3, A0, A1, A2, A3, kf1.x, kf1.y);   // keys kb+8..kb+15

        unsigned p01 = ex2_h2(h2_of(c0, c1));   // row g,   keys kb+2t4, kb+2t4+1
        unsigned p23 = ex2_h2(h2_of(c2, c3));   // row g+8, same keys
        unsigned e01 = ex2_h2(h2_of(d0, d1));   // row g,   keys kb+8+2t4, +1
        unsigned e23 = ex2_h2(h2_of(d2, d3));   // row g+8

        unsigned vb0 = sVh[((kb >> 1) + t4) * 8 + g];       // pairs for keys kb+2t4,+1
        unsigned vb1 = sVh[((kb >> 1) + 4 + t4) * 8 + g];   // keys kb+8+2t4,+1

        mma16h_acc(O0, O1, O2, O3, p01, p23, e01, e23, vb0, vb1);
        mma16h_acc(L0, L1, L2, L3, p01, p23, e01, e23, BONE, BONE);
    }

    // ---- epilogue: O and L complete per thread ----
    float r0 = 1.0f / L0;    // L0 = denominator of row g (all n cols identical)
    float r2 = 1.0f / L2;    // row g+8

    int bb_ = head >> 4;
    int hh  = head & 15;
    int row = qt * 128 + w * 16 + g;
    size_t base = (size_t)((bb_ << 10) + row) * E_DIM + hh * DK + 2 * t4;

    *reinterpret_cast<float2*>(g_attn + base)              = make_float2(O0 * r0, O1 * r0);
    *reinterpret_cast<float2*>(g_attn + base + 8 * E_DIM)  = make_float2(O2 * r2, O3 * r2);
}

// ---------------------------------------------------------------------------
// Kernel 3a: pack W into split B-fragments (hi/lo tf32).
// ---------------------------------------------------------------------------
__global__ void pack_w(const float* __restrict__ W) {
    int j = blockIdx.x * blockDim.x + threadIdx.x;
    if (j >= 16 * 16 * 32) return;
    int lane = j & 31;
    int et   = (j >> 5) & 15;
    int kt   = j >> 9;
    int g    = lane >> 2;
    int t4   = lane & 3;
    int e = et * 8 + g;
    int k = kt * 8 + t4;
    float w0 = __ldg(W + e * E_DIM + k);
    float w1 = __ldg(W + e * E_DIM + k + 4);
    unsigned h0 = tf32_of(w0), h1 = tf32_of(w1);
    float l0 = w0 - __uint_as_float(h0);
    float l1 = w1 - __uint_as_float(h1);
    g_wb[j] = make_uint4(h0, h1, __float_as_uint(l0), __float_as_uint(l1));
}

// ---------------------------------------------------------------------------
// Kernel 3b: combine as split-tf32 GEMM. Block = 256 thr = 8 warps:
// 32 rows x 32 e; warp (rh = w>>2, et = w&3). grid 512 -> ~27 warps/SM.
// ---------------------------------------------------------------------------
__global__ __launch_bounds__(256) void combine_kernel(float* __restrict__ out) {
    __shared__ __align__(16) float sa[32 * 132];   // 16.9 KB, conflict-free pitch

    int rb  = blockIdx.x >> 2;
    int eq  = blockIdx.x & 3;
    int row0 = rb * 32;
    int tid = threadIdx.x;
    int w   = tid >> 5;
    int lane = tid & 31;
    int g   = lane >> 2;
    int t4  = lane & 3;
    int rh  = w >> 2;
    int et  = w & 3;

    const float4* src = reinterpret_cast<const float4*>(g_attn + (size_t)row0 * E_DIM);
#pragma unroll
    for (int j = 0; j < 4; j++) {
        int idx = tid + j * 256;
        int r  = idx >> 5;
        int c4 = idx & 31;
        *reinterpret_cast<float4*>(sa + r * 132 + c4 * 4) = src[idx];
    }
    __syncthreads();

    float C0 = 0.f, C1 = 0.f, C2 = 0.f, C3 = 0.f;
    const float* sw = sa + (rh * 16 + g) * 132;

#pragma unroll
    for (int kt = 0; kt < 16; kt++) {
        int kb = kt * 8;
        float a0 = sw[kb + t4];
        float a1 = sw[8 * 132 + kb + t4];
        float a2 = sw[kb + t4 + 4];
        float a3 = sw[8 * 132 + kb + t4 + 4];
        unsigned h0 = tf32_of(a0), h1 = tf32_of(a1), h2 = tf32_of(a2), h3 = tf32_of(a3);
        unsigned l0 = __float_as_uint(a0 - __uint_as_float(h0));
        unsigned l1 = __float_as_uint(a1 - __uint_as_float(h1));
        unsigned l2 = __float_as_uint(a2 - __uint_as_float(h2));
        unsigned l3 = __float_as_uint(a3 - __uint_as_float(h3));

        uint4 B = __ldg(&g_wb[(kt * 16 + eq * 4 + et) * 32 + lane]);
        mma8_acc(C0, C1, C2, C3, h0, h1, h2, h3, B.x, B.y);
        mma8_acc(C0, C1, C2, C3, h0, h1, h2, h3, B.z, B.w);
        mma8_acc(C0, C1, C2, C3, l0, l1, l2, l3, B.x, B.y);
    }

    int r_g = row0 + rh * 16 + g;
    int e0  = eq * 32 + et * 8 + 2 * t4;
    *reinterpret_cast<float2*>(out + (size_t)r_g * E_DIM + e0) = make_float2(C0, C1);
    *reinterpret_cast<float2*>(out + (size_t)(r_g + 8) * E_DIM + e0) = make_float2(C2, C3);
}

// ---------------------------------------------------------------------------
extern "C" void kernel_launch(void* const* d_in, const int* in_sizes, int n_in,
                              void* d_out, int out_size) {
    const float* x  = nullptr;
    const float* rx = nullptr;
    const float* cw = nullptr;
    for (int i = 0; i < n_in; i++) {
        if (in_sizes[i] == NROWS * DK)          x  = (const float*)d_in[i];
        else if (in_sizes[i] == DK)             rx = (const float*)d_in[i];
        else if (in_sizes[i] == E_DIM * E_DIM)  cw = (const float*)d_in[i];
    }
    if (!x)  x  = (const float*)d_in[0];
    if (!rx) rx = (const float*)d_in[1];
    if (!cw) cw = (const float*)d_in[2];

    float* out = (float*)d_out;

    qkv_kernel<<<NROWS / 256, 256>>>(x, rx);
    pack_w<<<(16 * 16 * 32 + 255) / 256, 256>>>(cw);
    attn_kernel<<<NHEADS * 8, 256>>>();
    combine_kernel<<<512, 256>>>(out);
}